// round 2
// baseline (speedup 1.0000x reference)
#include <cuda_runtime.h>
#include <cuda_bf16.h>
#include <math.h>

#define NN   100000
#define EE   1600000
#define HID  128
#define OUTC 64
#define BNEPS 1e-5f

// ---------------- scratch (static device globals; no allocation) ----------------
__device__ int   g_deg[NN];
__device__ int   g_incl[NN];
__device__ int   g_bsum[128];
__device__ int   g_boff[128];
__device__ int   g_rowptr[NN + 1];
__device__ int   g_cursor[NN];
__device__ int   g_col[EE];
__device__ float g_invdeg[NN];
__device__ float g_agg[(size_t)NN * HID];
__device__ float g_h1[(size_t)NN * HID];
__device__ float g_h2[(size_t)NN * HID];

// ---------------- CSR build ----------------
__global__ void k_zero_deg() {
    int i = blockIdx.x * blockDim.x + threadIdx.x;
    if (i < NN) g_deg[i] = 0;
}

__global__ void k_count(const int* __restrict__ dst) {
    int e = blockIdx.x * blockDim.x + threadIdx.x;
    if (e < EE) atomicAdd(&g_deg[dst[e]], 1);
}

// per-block inclusive scan of g_deg (1024 elems/block)
__global__ void k_scan_block() {
    __shared__ int warpsums[32];
    int i = blockIdx.x * 1024 + threadIdx.x;
    int lane = threadIdx.x & 31;
    int warp = threadIdx.x >> 5;
    int v = (i < NN) ? g_deg[i] : 0;
    int x = v;
    #pragma unroll
    for (int d = 1; d < 32; d <<= 1) {
        int t = __shfl_up_sync(0xffffffffu, x, d);
        if (lane >= d) x += t;
    }
    if (lane == 31) warpsums[warp] = x;
    __syncthreads();
    if (threadIdx.x < 32) {
        int w = warpsums[threadIdx.x];
        int y = w;
        #pragma unroll
        for (int d = 1; d < 32; d <<= 1) {
            int t = __shfl_up_sync(0xffffffffu, y, d);
            if (threadIdx.x >= d) y += t;
        }
        warpsums[threadIdx.x] = y - w;  // exclusive warp offset
    }
    __syncthreads();
    x += warpsums[warp];
    if (i < NN) g_incl[i] = x;
    if (threadIdx.x == 1023) g_bsum[blockIdx.x] = x;
}

// scan the (<=128) block sums -> exclusive block offsets
__global__ void k_scan_tot(int nb) {
    __shared__ int ws[4];
    int t = threadIdx.x;
    int lane = t & 31;
    int warp = t >> 5;
    int v = (t < nb) ? g_bsum[t] : 0;
    int x = v;
    #pragma unroll
    for (int d = 1; d < 32; d <<= 1) {
        int tt = __shfl_up_sync(0xffffffffu, x, d);
        if (lane >= d) x += tt;
    }
    if (lane == 31) ws[warp] = x;
    __syncthreads();
    if (t == 0) {
        int a = 0;
        #pragma unroll
        for (int j = 0; j < 4; j++) { int tmp = ws[j]; ws[j] = a; a += tmp; }
    }
    __syncthreads();
    x += ws[warp];
    if (t < nb) g_boff[t] = x - v;  // exclusive
}

__global__ void k_finalize() {
    int i = blockIdx.x * blockDim.x + threadIdx.x;
    if (i < NN) {
        int d = g_deg[i];
        int rp = g_incl[i] + g_boff[i >> 10] - d;  // exclusive global scan
        g_rowptr[i] = rp;
        g_cursor[i] = rp;
        g_invdeg[i] = 1.0f / (float)max(d, 1);
    }
    if (i == 0) g_rowptr[NN] = EE;
}

__global__ void k_fill(const int* __restrict__ src, const int* __restrict__ dst) {
    int e = blockIdx.x * blockDim.x + threadIdx.x;
    if (e < EE) {
        int p = atomicAdd(&g_cursor[dst[e]], 1);
        g_col[p] = src[e];
    }
}

// ---------------- mean aggregation (one warp per node, gather via CSR) ----------------
__global__ void k_aggregate(const float* __restrict__ in, float* __restrict__ out) {
    int gw = (blockIdx.x * blockDim.x + threadIdx.x) >> 5;
    int lane = threadIdx.x & 31;
    if (gw >= NN) return;
    int s0 = g_rowptr[gw];
    int s1 = g_rowptr[gw + 1];
    float4 acc = make_float4(0.f, 0.f, 0.f, 0.f);
    for (int base = s0; base < s1; base += 32) {
        int cnt = s1 - base;
        if (cnt > 32) cnt = 32;
        int idxv = (lane < cnt) ? g_col[base + lane] : 0;
        for (int j = 0; j < cnt; j++) {
            int s = __shfl_sync(0xffffffffu, idxv, j);
            float4 v = *(const float4*)(in + (size_t)s * HID + lane * 4);
            acc.x += v.x; acc.y += v.y; acc.z += v.z; acc.w += v.w;
        }
    }
    float iv = g_invdeg[gw];
    acc.x *= iv; acc.y *= iv; acc.z *= iv; acc.w *= iv;
    *(float4*)(out + (size_t)gw * HID + lane * 4) = acc;
}

// ---------------- fused GEMM (+bias) + epilogue ----------------
// out[n][c] = sum_k agg[n][k]*Wl[c][k] + sum_k xin[n][k]*Wr[c][k] + b[c]
// EPI=0: BN (eval) + ReLU.  EPI=1: log_softmax over C.
// Block: 256 threads, weights (K2=256 x C) transposed in smem, tile of 32 nodes.
template <int C, int EPI>
__global__ void __launch_bounds__(256, 1)
k_gemm(const float* __restrict__ agg, const float* __restrict__ xin,
       const float* __restrict__ Wl, const float* __restrict__ Wr,
       const float* __restrict__ bias,
       const float* __restrict__ gam, const float* __restrict__ bet,
       const float* __restrict__ rmean, const float* __restrict__ rvar,
       float* __restrict__ out)
{
    constexpr int K2  = 2 * HID;   // 256
    constexpr int LDI = K2 + 4;    // padded input row stride
    constexpr int NR  = C / 32;    // cols per lane (4 or 2)
    static_assert(NR == 4 || NR == 2, "");

    extern __shared__ float sm[];
    float* sW  = sm;               // [K2][C] transposed weights
    float* sIn = sm + K2 * C;      // [32][LDI]

    int tid  = threadIdx.x;
    int warp = tid >> 5;
    int lane = tid & 31;

    // Load weights transposed: sW[k][c]. Read float4 along k (grouped), write
    // consecutive c (conflict-free STS).
    for (int idx = tid; idx < C * (K2 / 4); idx += 256) {
        int c  = idx % C;
        int kq = idx / C;
        int k4 = kq * 4;
        const float* wsrc = (k4 < HID) ? (Wl + (size_t)c * HID + k4)
                                       : (Wr + (size_t)c * HID + (k4 - HID));
        float4 w = *(const float4*)wsrc;
        sW[(k4 + 0) * C + c] = w.x;
        sW[(k4 + 1) * C + c] = w.y;
        sW[(k4 + 2) * C + c] = w.z;
        sW[(k4 + 3) * C + c] = w.w;
    }

    constexpr int NTILE = NN / 32;  // 3125 exact
    for (int tile = blockIdx.x; tile < NTILE; tile += gridDim.x) {
        __syncthreads();  // protect sIn from previous iteration's readers
        int nodebase = tile * 32;
        // cooperative load of 32 x 256 input tile (agg || xin), coalesced over k
        for (int idx = tid; idx < 32 * K2; idx += 256) {
            int ni = idx >> 8;
            int k  = idx & 255;
            float v = (k < HID) ? agg[(size_t)(nodebase + ni) * HID + k]
                                : xin[(size_t)(nodebase + ni) * HID + (k - HID)];
            sIn[ni * LDI + k] = v;
        }
        __syncthreads();

        float acc[4][NR];
        #pragma unroll
        for (int i = 0; i < 4; i++)
            #pragma unroll
            for (int j = 0; j < NR; j++) acc[i][j] = 0.f;

        const float* inbase = sIn + warp * 4 * LDI;

        #pragma unroll 4
        for (int k4 = 0; k4 < K2; k4 += 4) {
            float4 a[4];
            #pragma unroll
            for (int i = 0; i < 4; i++)
                a[i] = *(const float4*)(inbase + i * LDI + k4);
            #pragma unroll
            for (int kk = 0; kk < 4; kk++) {
                float w0, w1, w2 = 0.f, w3 = 0.f;
                if constexpr (NR == 4) {
                    float4 w = *(const float4*)(sW + (k4 + kk) * C + lane * 4);
                    w0 = w.x; w1 = w.y; w2 = w.z; w3 = w.w;
                } else {
                    float2 w = *(const float2*)(sW + (k4 + kk) * C + lane * 2);
                    w0 = w.x; w1 = w.y;
                }
                #pragma unroll
                for (int i = 0; i < 4; i++) {
                    float av = (kk == 0) ? a[i].x : (kk == 1) ? a[i].y
                             : (kk == 2) ? a[i].z : a[i].w;
                    acc[i][0] = fmaf(av, w0, acc[i][0]);
                    acc[i][1] = fmaf(av, w1, acc[i][1]);
                    if constexpr (NR == 4) {
                        acc[i][2] = fmaf(av, w2, acc[i][2]);
                        acc[i][3] = fmaf(av, w3, acc[i][3]);
                    }
                }
            }
        }

        int cbase = lane * NR;
        if constexpr (EPI == 0) {
            float4 bb  = *(const float4*)(bias  + cbase);
            float4 gg  = *(const float4*)(gam   + cbase);
            float4 be4 = *(const float4*)(bet   + cbase);
            float4 rm4 = *(const float4*)(rmean + cbase);
            float4 rv4 = *(const float4*)(rvar  + cbase);
            float sc0 = gg.x * rsqrtf(rv4.x + BNEPS);
            float sc1 = gg.y * rsqrtf(rv4.y + BNEPS);
            float sc2 = gg.z * rsqrtf(rv4.z + BNEPS);
            float sc3 = gg.w * rsqrtf(rv4.w + BNEPS);
            float sh0 = (bb.x - rm4.x) * sc0 + be4.x;
            float sh1 = (bb.y - rm4.y) * sc1 + be4.y;
            float sh2 = (bb.z - rm4.z) * sc2 + be4.z;
            float sh3 = (bb.w - rm4.w) * sc3 + be4.w;
            #pragma unroll
            for (int i = 0; i < 4; i++) {
                int node = nodebase + warp * 4 + i;
                float4 o;
                o.x = fmaxf(fmaf(acc[i][0], sc0, sh0), 0.f);
                o.y = fmaxf(fmaf(acc[i][1], sc1, sh1), 0.f);
                o.z = fmaxf(fmaf(acc[i][2], sc2, sh2), 0.f);
                o.w = fmaxf(fmaf(acc[i][3], sc3, sh3), 0.f);
                *(float4*)(out + (size_t)node * C + cbase) = o;
            }
        } else {
            float2 bb = *(const float2*)(bias + cbase);
            #pragma unroll
            for (int i = 0; i < 4; i++) {
                float l0 = acc[i][0] + bb.x;
                float l1 = acc[i][1] + bb.y;
                float m = fmaxf(l0, l1);
                #pragma unroll
                for (int o = 16; o; o >>= 1)
                    m = fmaxf(m, __shfl_xor_sync(0xffffffffu, m, o));
                float s = expf(l0 - m) + expf(l1 - m);
                #pragma unroll
                for (int o = 16; o; o >>= 1)
                    s += __shfl_xor_sync(0xffffffffu, s, o);
                float lse = m + logf(s);
                int node = nodebase + warp * 4 + i;
                float2 o2;
                o2.x = l0 - lse;
                o2.y = l1 - lse;
                *(float2*)(out + (size_t)node * OUTC + cbase) = o2;
            }
        }
    }
}

// ---------------- launch ----------------
extern "C" void kernel_launch(void* const* d_in, const int* in_sizes, int n_in,
                              void* d_out, int out_size)
{
    const float* x   = (const float*)d_in[0];
    const int*   src = (const int*)d_in[1];
    const int*   dst = (const int*)d_in[2];
    const float* W1l = (const float*)d_in[3];
    const float* W1r = (const float*)d_in[4];
    const float* b1  = (const float*)d_in[5];
    const float* g1  = (const float*)d_in[6];
    const float* be1 = (const float*)d_in[7];
    const float* rm1 = (const float*)d_in[8];
    const float* rv1 = (const float*)d_in[9];
    const float* W2l = (const float*)d_in[10];
    const float* W2r = (const float*)d_in[11];
    const float* b2  = (const float*)d_in[12];
    const float* g2  = (const float*)d_in[13];
    const float* be2 = (const float*)d_in[14];
    const float* rm2 = (const float*)d_in[15];
    const float* rv2 = (const float*)d_in[16];
    const float* W3l = (const float*)d_in[17];
    const float* W3r = (const float*)d_in[18];
    const float* b3  = (const float*)d_in[19];
    float* out = (float*)d_out;

    float *agg, *h1, *h2;
    cudaGetSymbolAddress((void**)&agg, g_agg);
    cudaGetSymbolAddress((void**)&h1,  g_h1);
    cudaGetSymbolAddress((void**)&h2,  g_h2);

    const int NB = (NN + 1023) >> 10;  // 98 scan blocks

    // CSR build (reused by all 3 layers)
    k_zero_deg<<<(NN + 255) / 256, 256>>>();
    k_count<<<(EE + 255) / 256, 256>>>(dst);
    k_scan_block<<<NB, 1024>>>();
    k_scan_tot<<<1, 128>>>(NB);
    k_finalize<<<(NN + 255) / 256, 256>>>();
    k_fill<<<(EE + 255) / 256, 256>>>(src, dst);

    constexpr int K2 = 2 * HID;
    const int SM128 = (K2 * 128 + 32 * (K2 + 4)) * 4;  // 164352 B
    const int SM64  = (K2 * 64  + 32 * (K2 + 4)) * 4;  //  98816 B
    cudaFuncSetAttribute(k_gemm<128, 0>, cudaFuncAttributeMaxDynamicSharedMemorySize, SM128);
    cudaFuncSetAttribute(k_gemm<64, 1>,  cudaFuncAttributeMaxDynamicSharedMemorySize, SM64);

    const int AGG_BLOCKS = (NN * 32 + 255) / 256;  // one warp per node

    // Layer 1
    k_aggregate<<<AGG_BLOCKS, 256>>>(x, agg);
    k_gemm<128, 0><<<148, 256, SM128>>>(agg, x, W1l, W1r, b1, g1, be1, rm1, rv1, h1);
    // Layer 2
    k_aggregate<<<AGG_BLOCKS, 256>>>(h1, agg);
    k_gemm<128, 0><<<148, 256, SM128>>>(agg, h1, W2l, W2r, b2, g2, be2, rm2, rv2, h2);
    // Layer 3 + log_softmax
    k_aggregate<<<AGG_BLOCKS, 256>>>(h2, agg);
    k_gemm<64, 1><<<148, 256, SM64>>>(agg, h2, W3l, W3r, b3,
                                      nullptr, nullptr, nullptr, nullptr, out);
}

// round 5
// speedup vs baseline: 2.1195x; 2.1195x over previous
#include <cuda_runtime.h>
#include <cuda_bf16.h>
#include <cstdint>
#include <math.h>

#define NN   100000
#define EE   1600000
#define HID  128
#define OUTC 64
#define BNEPS 1e-5f

// ---------------- scratch (static device globals; no allocation) ----------------
__device__ int   g_deg[NN];
__device__ int   g_incl[NN];
__device__ int   g_bsum[128];
__device__ int   g_boff[128];
__device__ int   g_rowptr[NN + 1];
__device__ int   g_cursor[NN];
__device__ int   g_col[EE];
__device__ float g_invdeg[NN];
__device__ float g_u[(size_t)NN * HID];   // projected "left" features (to aggregate)
__device__ float g_v[(size_t)NN * HID];   // projected "right" features (self)
__device__ float g_h[(size_t)NN * HID];   // layer activations

// ---------------- CSR build ----------------
__global__ void k_zero_deg() {
    int i = blockIdx.x * blockDim.x + threadIdx.x;
    if (i < NN) g_deg[i] = 0;
}
__global__ void k_count(const int* __restrict__ dst) {
    int e = blockIdx.x * blockDim.x + threadIdx.x;
    if (e < EE) atomicAdd(&g_deg[dst[e]], 1);
}
__global__ void k_scan_block() {
    __shared__ int warpsums[32];
    int i = blockIdx.x * 1024 + threadIdx.x;
    int lane = threadIdx.x & 31, warp = threadIdx.x >> 5;
    int v = (i < NN) ? g_deg[i] : 0;
    int x = v;
    #pragma unroll
    for (int d = 1; d < 32; d <<= 1) { int t = __shfl_up_sync(~0u, x, d); if (lane >= d) x += t; }
    if (lane == 31) warpsums[warp] = x;
    __syncthreads();
    if (threadIdx.x < 32) {
        int w = warpsums[threadIdx.x]; int y = w;
        #pragma unroll
        for (int d = 1; d < 32; d <<= 1) { int t = __shfl_up_sync(~0u, y, d); if (threadIdx.x >= d) y += t; }
        warpsums[threadIdx.x] = y - w;
    }
    __syncthreads();
    x += warpsums[warp];
    if (i < NN) g_incl[i] = x;
    if (threadIdx.x == 1023) g_bsum[blockIdx.x] = x;
}
__global__ void k_scan_tot(int nb) {
    __shared__ int ws[4];
    int t = threadIdx.x, lane = t & 31, warp = t >> 5;
    int v = (t < nb) ? g_bsum[t] : 0;
    int x = v;
    #pragma unroll
    for (int d = 1; d < 32; d <<= 1) { int tt = __shfl_up_sync(~0u, x, d); if (lane >= d) x += tt; }
    if (lane == 31) ws[warp] = x;
    __syncthreads();
    if (t == 0) { int a = 0; for (int j = 0; j < 4; j++) { int tmp = ws[j]; ws[j] = a; a += tmp; } }
    __syncthreads();
    x += ws[warp];
    if (t < nb) g_boff[t] = x - v;
}
__global__ void k_finalize() {
    int i = blockIdx.x * blockDim.x + threadIdx.x;
    if (i < NN) {
        int d = g_deg[i];
        int rp = g_incl[i] + g_boff[i >> 10] - d;
        g_rowptr[i] = rp;
        g_cursor[i] = rp;
        g_invdeg[i] = 1.0f / (float)max(d, 1);
    }
    if (i == 0) g_rowptr[NN] = EE;
}
__global__ void k_fill(const int* __restrict__ src, const int* __restrict__ dst) {
    int e = blockIdx.x * blockDim.x + threadIdx.x;
    if (e < EE) { int p = atomicAdd(&g_cursor[dst[e]], 1); g_col[p] = src[e]; }
}

// ================= HMMA helpers (portable sm_80+ PTX) =================
__device__ __forceinline__ uint32_t smem_u32(const void* p) {
    uint32_t a;
    asm("{ .reg .u64 t; cvta.to.shared.u64 t, %1; cvt.u32.u64 %0, t; }" : "=r"(a) : "l"(p));
    return a;
}
__device__ __forceinline__ void ldm_x4(uint32_t* r, uint32_t addr) {
    asm volatile("ldmatrix.sync.aligned.m8n8.x4.shared.b16 {%0,%1,%2,%3}, [%4];"
        : "=r"(r[0]), "=r"(r[1]), "=r"(r[2]), "=r"(r[3]) : "r"(addr));
}
__device__ __forceinline__ void mma16816(float* d, const uint32_t* a, const uint32_t* b) {
    asm volatile("mma.sync.aligned.m16n8k16.row.col.f32.bf16.bf16.f32 "
        "{%0,%1,%2,%3}, {%4,%5,%6,%7}, {%8,%9}, {%0,%1,%2,%3};"
        : "+f"(d[0]), "+f"(d[1]), "+f"(d[2]), "+f"(d[3])
        : "r"(a[0]), "r"(a[1]), "r"(a[2]), "r"(a[3]), "r"(b[0]), "r"(b[1]));
}
// fp32 pair -> hi bf16x2 (ret) + lo bf16x2 (out param)
__device__ __forceinline__ uint32_t bfsplit2(float a, float b, uint32_t& lo) {
    __nv_bfloat16 h0 = __float2bfloat16_rn(a), h1 = __float2bfloat16_rn(b);
    float r0 = a - __bfloat162float(h0), r1 = b - __bfloat162float(h1);
    __nv_bfloat16 l0 = __float2bfloat16_rn(r0), l1 = __float2bfloat16_rn(r1);
    lo = (uint32_t)__bfloat16_as_ushort(l0) | ((uint32_t)__bfloat16_as_ushort(l1) << 16);
    return (uint32_t)__bfloat16_as_ushort(h0) | ((uint32_t)__bfloat16_as_ushort(h1) << 16);
}
// swizzled smem address: row stride 256B (128 bf16), 16B chunks XORed by row&7
__device__ __forceinline__ uint32_t swaddr(uint32_t base, int row, int chunk) {
    return base + (uint32_t)(row * 256) + (uint32_t)(((chunk ^ (row & 7)) << 4));
}

// ================= bf16 split-precision GEMM via mma.sync =================
// out[node][cg] = sum_k A[node][k] * W[cg][k],  W = [Wl ; Wr] stacked (NOUT rows).
// CTA: 512 thr, 16 warps (4m x 4n), tile 128 nodes x 128 cols, persistent over m-tiles.
// Cols [0,NH) -> uout, [NH,NOUT) -> vout (row stride NH each).
template <int NOUT>
__global__ void __launch_bounds__(512, 1)
k_mma_gemm(const float* __restrict__ Ain,
           const float* __restrict__ Wl, const float* __restrict__ Wr,
           float* __restrict__ uout, float* __restrict__ vout)
{
    constexpr int NH = NOUT / 2;
    constexpr int NTILES = (NN + 127) / 128;
    constexpr uint32_t OFF_WH = 0, OFF_WL = 32768, OFF_AH = 65536, OFF_AL = 98304;

    extern __shared__ char sm[];
    uint32_t sb = smem_u32(sm);

    int tid = threadIdx.x;
    int wid = tid >> 5;
    int lane = tid & 31;
    int wm = wid & 3, wn = wid >> 2;
    int by = blockIdx.y;

    // ---- stage weights once (128 rows x 128 k, hi/lo) ----
    for (int idx = tid; idx < 128 * 32; idx += 512) {
        int r = idx >> 5, q = idx & 31;
        int gcol = by * 128 + r;
        const float* ws = (gcol < NH) ? (Wl + (size_t)gcol * HID + q * 4)
                                      : (Wr + (size_t)(gcol - NH) * HID + q * 4);
        float4 w = *(const float4*)ws;
        uint32_t l01, l23;
        uint32_t h01 = bfsplit2(w.x, w.y, l01);
        uint32_t h23 = bfsplit2(w.z, w.w, l23);
        uint32_t a = swaddr(sb, r, q >> 1) + (q & 1) * 8;
        *(uint2*)(sm + (a - sb) + OFF_WH) = make_uint2(h01, h23);
        *(uint2*)(sm + (a - sb) + OFF_WL) = make_uint2(l01, l23);
    }

    int lane15 = lane & 15, lhalf = lane >> 4;
    int t4 = lane & 3, g8 = lane >> 2;
    int mrow = wm * 32 + lane15;   // ldmatrix row for A (mi adds 16)
    int nrow = wn * 32 + lane15;   // ldmatrix row for W (nj adds 16)

    for (int tile = blockIdx.x; tile < NTILES; tile += gridDim.x) {
        int nodebase = tile * 128;
        __syncthreads();   // previous tile fully consumed

        // ---- stage A tile (128 rows x 128 k, hi/lo) ----
        for (int idx = tid; idx < 128 * 32; idx += 512) {
            int r = idx >> 5, q = idx & 31;
            int node = nodebase + r;
            float4 av = (node < NN) ? *(const float4*)(Ain + (size_t)node * HID + q * 4)
                                    : make_float4(0.f, 0.f, 0.f, 0.f);
            uint32_t l01, l23;
            uint32_t h01 = bfsplit2(av.x, av.y, l01);
            uint32_t h23 = bfsplit2(av.z, av.w, l23);
            uint32_t a = swaddr(sb, r, q >> 1) + (q & 1) * 8;
            *(uint2*)(sm + (a - sb) + OFF_AH) = make_uint2(h01, h23);
            *(uint2*)(sm + (a - sb) + OFF_AL) = make_uint2(l01, l23);
        }
        __syncthreads();

        // ---- compute: 8 k-steps, 3-way split, fp32 acc ----
        float acc[2][4][4];
        #pragma unroll
        for (int i = 0; i < 2; i++)
            #pragma unroll
            for (int j = 0; j < 4; j++)
                #pragma unroll
                for (int e = 0; e < 4; e++) acc[i][j][e] = 0.f;

        #pragma unroll
        for (int ks = 0; ks < 8; ks++) {
            int ch = ks * 2 + lhalf;
            uint32_t Ah[2][4], Al[2][4], Bh[4][2], Bl[4][2], tb[4];
            ldm_x4(Ah[0], swaddr(sb + OFF_AH, mrow,      ch));
            ldm_x4(Ah[1], swaddr(sb + OFF_AH, mrow + 16, ch));
            ldm_x4(Al[0], swaddr(sb + OFF_AL, mrow,      ch));
            ldm_x4(Al[1], swaddr(sb + OFF_AL, mrow + 16, ch));
            ldm_x4(tb, swaddr(sb + OFF_WH, nrow, ch));
            Bh[0][0] = tb[0]; Bh[0][1] = tb[2]; Bh[1][0] = tb[1]; Bh[1][1] = tb[3];
            ldm_x4(tb, swaddr(sb + OFF_WH, nrow + 16, ch));
            Bh[2][0] = tb[0]; Bh[2][1] = tb[2]; Bh[3][0] = tb[1]; Bh[3][1] = tb[3];
            ldm_x4(tb, swaddr(sb + OFF_WL, nrow, ch));
            Bl[0][0] = tb[0]; Bl[0][1] = tb[2]; Bl[1][0] = tb[1]; Bl[1][1] = tb[3];
            ldm_x4(tb, swaddr(sb + OFF_WL, nrow + 16, ch));
            Bl[2][0] = tb[0]; Bl[2][1] = tb[2]; Bl[3][0] = tb[1]; Bl[3][1] = tb[3];

            #pragma unroll
            for (int mi = 0; mi < 2; mi++)
                #pragma unroll
                for (int nf = 0; nf < 4; nf++) {
                    mma16816(acc[mi][nf], Ah[mi], Bh[nf]);
                    mma16816(acc[mi][nf], Al[mi], Bh[nf]);
                    mma16816(acc[mi][nf], Ah[mi], Bl[nf]);
                }
        }

        // ---- epilogue: direct global float2 stores ----
        #pragma unroll
        for (int mi = 0; mi < 2; mi++) {
            int row0 = nodebase + wm * 32 + mi * 16 + g8;
            #pragma unroll
            for (int nf = 0; nf < 4; nf++) {
                int cg = by * 128 + wn * 32 + nf * 8 + 2 * t4;
                float* dp = (cg < NH) ? (uout + cg) : (vout + (cg - NH));
                if (row0 < NN)
                    *(float2*)(dp + (size_t)row0 * NH) =
                        make_float2(acc[mi][nf][0], acc[mi][nf][1]);
                if (row0 + 8 < NN)
                    *(float2*)(dp + (size_t)(row0 + 8) * NH) =
                        make_float2(acc[mi][nf][2], acc[mi][nf][3]);
            }
        }
    }
}

// ---------------- fused mean-aggregate + bias + BN + ReLU (layers 1,2) ----------------
__global__ void k_agg_bn(const float* __restrict__ u, const float* __restrict__ v,
                         const float* __restrict__ bias, const float* __restrict__ gam,
                         const float* __restrict__ bet, const float* __restrict__ rmean,
                         const float* __restrict__ rvar, float* __restrict__ hout)
{
    int gw = (blockIdx.x * blockDim.x + threadIdx.x) >> 5;
    int lane = threadIdx.x & 31;
    if (gw >= NN) return;
    int s0 = g_rowptr[gw], s1 = g_rowptr[gw + 1];
    float4 acc = make_float4(0.f, 0.f, 0.f, 0.f);
    for (int b = s0; b < s1; b += 32) {
        int cnt = s1 - b; if (cnt > 32) cnt = 32;
        int idxv = (lane < cnt) ? g_col[b + lane] : 0;
        for (int j = 0; j < cnt; j++) {
            int s = __shfl_sync(~0u, idxv, j);
            float4 t = *(const float4*)(u + (size_t)s * HID + lane * 4);
            acc.x += t.x; acc.y += t.y; acc.z += t.z; acc.w += t.w;
        }
    }
    float iv = g_invdeg[gw];
    int cb = lane * 4;
    float4 vv = *(const float4*)(v + (size_t)gw * HID + cb);
    float4 bb = *(const float4*)(bias + cb);
    float4 gg = *(const float4*)(gam + cb);
    float4 be = *(const float4*)(bet + cb);
    float4 rm = *(const float4*)(rmean + cb);
    float4 rv = *(const float4*)(rvar + cb);
    float4 o;
    o.x = fmaxf((acc.x * iv + bb.x + vv.x - rm.x) * (gg.x * rsqrtf(rv.x + BNEPS)) + be.x, 0.f);
    o.y = fmaxf((acc.y * iv + bb.y + vv.y - rm.y) * (gg.y * rsqrtf(rv.y + BNEPS)) + be.y, 0.f);
    o.z = fmaxf((acc.z * iv + bb.z + vv.z - rm.z) * (gg.z * rsqrtf(rv.z + BNEPS)) + be.z, 0.f);
    o.w = fmaxf((acc.w * iv + bb.w + vv.w - rm.w) * (gg.w * rsqrtf(rv.w + BNEPS)) + be.w, 0.f);
    *(float4*)(hout + (size_t)gw * HID + cb) = o;
}

// ---------------- layer 3: mean-aggregate(p) + b3 + r, log_softmax ----------------
__global__ void k_agg_lsm(const float* __restrict__ p, const float* __restrict__ r,
                          const float* __restrict__ b3, float* __restrict__ out)
{
    int gw = (blockIdx.x * blockDim.x + threadIdx.x) >> 5;
    int lane = threadIdx.x & 31;
    if (gw >= NN) return;
    int s0 = g_rowptr[gw], s1 = g_rowptr[gw + 1];
    float ax = 0.f, ay = 0.f;
    for (int b = s0; b < s1; b += 32) {
        int cnt = s1 - b; if (cnt > 32) cnt = 32;
        int idxv = (lane < cnt) ? g_col[b + lane] : 0;
        for (int j = 0; j < cnt; j++) {
            int s = __shfl_sync(~0u, idxv, j);
            float2 t = *(const float2*)(p + (size_t)s * OUTC + lane * 2);
            ax += t.x; ay += t.y;
        }
    }
    float iv = g_invdeg[gw];
    float2 rr = *(const float2*)(r + (size_t)gw * OUTC + lane * 2);
    float2 bb = *(const float2*)(b3 + lane * 2);
    float l0 = ax * iv + bb.x + rr.x;
    float l1 = ay * iv + bb.y + rr.y;
    float m = fmaxf(l0, l1);
    #pragma unroll
    for (int o = 16; o; o >>= 1) m = fmaxf(m, __shfl_xor_sync(~0u, m, o));
    float s = expf(l0 - m) + expf(l1 - m);
    #pragma unroll
    for (int o = 16; o; o >>= 1) s += __shfl_xor_sync(~0u, s, o);
    float lse = m + logf(s);
    float2 o2; o2.x = l0 - lse; o2.y = l1 - lse;
    *(float2*)(out + (size_t)gw * OUTC + lane * 2) = o2;
}

// ---------------- launch ----------------
extern "C" void kernel_launch(void* const* d_in, const int* in_sizes, int n_in,
                              void* d_out, int out_size)
{
    const float* x   = (const float*)d_in[0];
    const int*   src = (const int*)d_in[1];
    const int*   dst = (const int*)d_in[2];
    const float* W1l = (const float*)d_in[3];
    const float* W1r = (const float*)d_in[4];
    const float* b1  = (const float*)d_in[5];
    const float* g1  = (const float*)d_in[6];
    const float* be1 = (const float*)d_in[7];
    const float* rm1 = (const float*)d_in[8];
    const float* rv1 = (const float*)d_in[9];
    const float* W2l = (const float*)d_in[10];
    const float* W2r = (const float*)d_in[11];
    const float* b2  = (const float*)d_in[12];
    const float* g2  = (const float*)d_in[13];
    const float* be2 = (const float*)d_in[14];
    const float* rm2 = (const float*)d_in[15];
    const float* rv2 = (const float*)d_in[16];
    const float* W3l = (const float*)d_in[17];
    const float* W3r = (const float*)d_in[18];
    const float* b3  = (const float*)d_in[19];
    float* out = (float*)d_out;

    float *u, *v, *h;
    cudaGetSymbolAddress((void**)&u, g_u);
    cudaGetSymbolAddress((void**)&v, g_v);
    cudaGetSymbolAddress((void**)&h, g_h);

    const int NB = (NN + 1023) >> 10;

    // CSR build (shared by all layers)
    k_zero_deg<<<(NN + 255) / 256, 256>>>();
    k_count<<<(EE + 255) / 256, 256>>>(dst);
    k_scan_block<<<NB, 1024>>>();
    k_scan_tot<<<1, 128>>>(NB);
    k_finalize<<<(NN + 255) / 256, 256>>>();
    k_fill<<<(EE + 255) / 256, 256>>>(src, dst);

    const int SMEM = 131072;  // Whi+Wlo+Ahi+Alo, 32KB each
    cudaFuncSetAttribute(k_mma_gemm<256>, cudaFuncAttributeMaxDynamicSharedMemorySize, SMEM);
    cudaFuncSetAttribute(k_mma_gemm<128>, cudaFuncAttributeMaxDynamicSharedMemorySize, SMEM);

    const int AGG_BLOCKS = (NN * 32 + 255) / 256;

    // Layer 1: project x -> [u|v], then mean(u)+b+v -> BN -> ReLU -> h
    k_mma_gemm<256><<<dim3(74, 2), 512, SMEM>>>(x, W1l, W1r, u, v);
    k_agg_bn<<<AGG_BLOCKS, 256>>>(u, v, b1, g1, be1, rm1, rv1, h);
    // Layer 2
    k_mma_gemm<256><<<dim3(74, 2), 512, SMEM>>>(h, W2l, W2r, u, v);
    k_agg_bn<<<AGG_BLOCKS, 256>>>(u, v, b2, g2, be2, rm2, rv2, h);
    // Layer 3: project h -> [p|r] (64 each), aggregate p, add b3+r, log_softmax
    k_mma_gemm<128><<<dim3(148, 1), 512, SMEM>>>(h, W3l, W3r, u, v);
    k_agg_lsm<<<AGG_BLOCKS, 256>>>(u, v, b3, out);
}

// round 6
// speedup vs baseline: 2.3259x; 1.0974x over previous
#include <cuda_runtime.h>
#include <cuda_bf16.h>
#include <cuda_fp16.h>
#include <cstdint>
#include <math.h>

#define NN   100000
#define EE   1600000
#define HID  128
#define OUTC 64
#define BNEPS 1e-5f

// ---------------- scratch (static device globals; no allocation) ----------------
__device__ int   g_deg[NN];
__device__ int   g_incl[NN];
__device__ int   g_bsum[128];
__device__ int   g_boff[128];
__device__ int   g_rowptr[NN + 1];
__device__ int   g_cursor[NN];
__device__ int   g_col[EE];
__device__ float g_invdeg[NN];
__device__ __half g_u[(size_t)NN * HID];  // projected "left" features (to aggregate), fp16
__device__ float g_v[(size_t)NN * HID];   // projected "right" features (self), fp32
__device__ float g_h[(size_t)NN * HID];   // layer activations

// ---------------- CSR build ----------------
__global__ void k_zero_deg() {
    int i = blockIdx.x * blockDim.x + threadIdx.x;
    if (i < NN) g_deg[i] = 0;
}
__global__ void k_count(const int* __restrict__ dst) {
    int e = blockIdx.x * blockDim.x + threadIdx.x;
    if (e < EE) atomicAdd(&g_deg[dst[e]], 1);
}
__global__ void k_scan_block() {
    __shared__ int warpsums[32];
    int i = blockIdx.x * 1024 + threadIdx.x;
    int lane = threadIdx.x & 31, warp = threadIdx.x >> 5;
    int v = (i < NN) ? g_deg[i] : 0;
    int x = v;
    #pragma unroll
    for (int d = 1; d < 32; d <<= 1) { int t = __shfl_up_sync(~0u, x, d); if (lane >= d) x += t; }
    if (lane == 31) warpsums[warp] = x;
    __syncthreads();
    if (threadIdx.x < 32) {
        int w = warpsums[threadIdx.x]; int y = w;
        #pragma unroll
        for (int d = 1; d < 32; d <<= 1) { int t = __shfl_up_sync(~0u, y, d); if (threadIdx.x >= d) y += t; }
        warpsums[threadIdx.x] = y - w;
    }
    __syncthreads();
    x += warpsums[warp];
    if (i < NN) g_incl[i] = x;
    if (threadIdx.x == 1023) g_bsum[blockIdx.x] = x;
}
__global__ void k_scan_tot(int nb) {
    __shared__ int ws[4];
    int t = threadIdx.x, lane = t & 31, warp = t >> 5;
    int v = (t < nb) ? g_bsum[t] : 0;
    int x = v;
    #pragma unroll
    for (int d = 1; d < 32; d <<= 1) { int tt = __shfl_up_sync(~0u, x, d); if (lane >= d) x += tt; }
    if (lane == 31) ws[warp] = x;
    __syncthreads();
    if (t == 0) { int a = 0; for (int j = 0; j < 4; j++) { int tmp = ws[j]; ws[j] = a; a += tmp; } }
    __syncthreads();
    x += ws[warp];
    if (t < nb) g_boff[t] = x - v;
}
__global__ void k_finalize() {
    int i = blockIdx.x * blockDim.x + threadIdx.x;
    if (i < NN) {
        int d = g_deg[i];
        int rp = g_incl[i] + g_boff[i >> 10] - d;
        g_rowptr[i] = rp;
        g_cursor[i] = rp;
        g_invdeg[i] = 1.0f / (float)max(d, 1);
    }
    if (i == 0) g_rowptr[NN] = EE;
}
__global__ void k_fill(const int* __restrict__ src, const int* __restrict__ dst) {
    int e = blockIdx.x * blockDim.x + threadIdx.x;
    if (e < EE) { int p = atomicAdd(&g_cursor[dst[e]], 1); g_col[p] = src[e]; }
}

// ================= HMMA helpers (portable sm_80+ PTX) =================
__device__ __forceinline__ uint32_t smem_u32(const void* p) {
    uint32_t a;
    asm("{ .reg .u64 t; cvta.to.shared.u64 t, %1; cvt.u32.u64 %0, t; }" : "=r"(a) : "l"(p));
    return a;
}
__device__ __forceinline__ void ldm_x4(uint32_t* r, uint32_t addr) {
    asm volatile("ldmatrix.sync.aligned.m8n8.x4.shared.b16 {%0,%1,%2,%3}, [%4];"
        : "=r"(r[0]), "=r"(r[1]), "=r"(r[2]), "=r"(r[3]) : "r"(addr));
}
__device__ __forceinline__ void mma16816(float* d, const uint32_t* a, const uint32_t* b) {
    asm volatile("mma.sync.aligned.m16n8k16.row.col.f32.bf16.bf16.f32 "
        "{%0,%1,%2,%3}, {%4,%5,%6,%7}, {%8,%9}, {%0,%1,%2,%3};"
        : "+f"(d[0]), "+f"(d[1]), "+f"(d[2]), "+f"(d[3])
        : "r"(a[0]), "r"(a[1]), "r"(a[2]), "r"(a[3]), "r"(b[0]), "r"(b[1]));
}
// fp32 pair -> hi bf16x2 (ret) + lo bf16x2 (out param)
__device__ __forceinline__ uint32_t bfsplit2(float a, float b, uint32_t& lo) {
    __nv_bfloat16 h0 = __float2bfloat16_rn(a), h1 = __float2bfloat16_rn(b);
    float r0 = a - __bfloat162float(h0), r1 = b - __bfloat162float(h1);
    __nv_bfloat16 l0 = __float2bfloat16_rn(r0), l1 = __float2bfloat16_rn(r1);
    lo = (uint32_t)__bfloat16_as_ushort(l0) | ((uint32_t)__bfloat16_as_ushort(l1) << 16);
    return (uint32_t)__bfloat16_as_ushort(h0) | ((uint32_t)__bfloat16_as_ushort(h1) << 16);
}
// swizzled smem address: row stride 256B (128 bf16), 16B chunks XORed by row&7
__device__ __forceinline__ uint32_t swaddr(uint32_t base, int row, int chunk) {
    return base + (uint32_t)(row * 256) + (uint32_t)(((chunk ^ (row & 7)) << 4));
}

// ================= bf16 split-precision GEMM via mma.sync =================
// out[node][cg] = sum_k A[node][k] * W[cg][k],  W = [Wl ; Wr] stacked (NOUT rows).
// CTA: 512 thr, 16 warps (4m x 4n), tile 128 nodes x 128 cols, persistent over m-tiles.
// Cols [0,NH) -> uout (fp16), [NH,NOUT) -> vout (fp32); row stride NH each.
template <int NOUT>
__global__ void __launch_bounds__(512, 1)
k_mma_gemm(const float* __restrict__ Ain,
           const float* __restrict__ Wl, const float* __restrict__ Wr,
           __half* __restrict__ uout, float* __restrict__ vout)
{
    constexpr int NH = NOUT / 2;
    constexpr int NTILES = (NN + 127) / 128;
    constexpr uint32_t OFF_WH = 0, OFF_WL = 32768, OFF_AH = 65536, OFF_AL = 98304;

    extern __shared__ char sm[];
    uint32_t sb = smem_u32(sm);

    int tid = threadIdx.x;
    int wid = tid >> 5;
    int lane = tid & 31;
    int wm = wid & 3, wn = wid >> 2;
    int by = blockIdx.y;

    // ---- stage weights once (128 rows x 128 k, hi/lo) ----
    for (int idx = tid; idx < 128 * 32; idx += 512) {
        int r = idx >> 5, q = idx & 31;
        int gcol = by * 128 + r;
        const float* ws = (gcol < NH) ? (Wl + (size_t)gcol * HID + q * 4)
                                      : (Wr + (size_t)(gcol - NH) * HID + q * 4);
        float4 w = *(const float4*)ws;
        uint32_t l01, l23;
        uint32_t h01 = bfsplit2(w.x, w.y, l01);
        uint32_t h23 = bfsplit2(w.z, w.w, l23);
        uint32_t a = swaddr(sb, r, q >> 1) + (q & 1) * 8;
        *(uint2*)(sm + (a - sb) + OFF_WH) = make_uint2(h01, h23);
        *(uint2*)(sm + (a - sb) + OFF_WL) = make_uint2(l01, l23);
    }

    int lane15 = lane & 15, lhalf = lane >> 4;
    int t4 = lane & 3, g8 = lane >> 2;
    int mrow = wm * 32 + lane15;
    int nrow = wn * 32 + lane15;

    for (int tile = blockIdx.x; tile < NTILES; tile += gridDim.x) {
        int nodebase = tile * 128;
        __syncthreads();   // previous tile fully consumed

        // ---- stage A tile (128 rows x 128 k, hi/lo) ----
        for (int idx = tid; idx < 128 * 32; idx += 512) {
            int r = idx >> 5, q = idx & 31;
            int node = nodebase + r;
            float4 av = (node < NN) ? *(const float4*)(Ain + (size_t)node * HID + q * 4)
                                    : make_float4(0.f, 0.f, 0.f, 0.f);
            uint32_t l01, l23;
            uint32_t h01 = bfsplit2(av.x, av.y, l01);
            uint32_t h23 = bfsplit2(av.z, av.w, l23);
            uint32_t a = swaddr(sb, r, q >> 1) + (q & 1) * 8;
            *(uint2*)(sm + (a - sb) + OFF_AH) = make_uint2(h01, h23);
            *(uint2*)(sm + (a - sb) + OFF_AL) = make_uint2(l01, l23);
        }
        __syncthreads();

        // ---- compute: 8 k-steps, 3-way split, fp32 acc ----
        float acc[2][4][4];
        #pragma unroll
        for (int i = 0; i < 2; i++)
            #pragma unroll
            for (int j = 0; j < 4; j++)
                #pragma unroll
                for (int e = 0; e < 4; e++) acc[i][j][e] = 0.f;

        #pragma unroll
        for (int ks = 0; ks < 8; ks++) {
            int ch = ks * 2 + lhalf;
            uint32_t Ah[2][4], Al[2][4], Bh[4][2], Bl[4][2], tb[4];
            ldm_x4(Ah[0], swaddr(sb + OFF_AH, mrow,      ch));
            ldm_x4(Ah[1], swaddr(sb + OFF_AH, mrow + 16, ch));
            ldm_x4(Al[0], swaddr(sb + OFF_AL, mrow,      ch));
            ldm_x4(Al[1], swaddr(sb + OFF_AL, mrow + 16, ch));
            ldm_x4(tb, swaddr(sb + OFF_WH, nrow, ch));
            Bh[0][0] = tb[0]; Bh[0][1] = tb[2]; Bh[1][0] = tb[1]; Bh[1][1] = tb[3];
            ldm_x4(tb, swaddr(sb + OFF_WH, nrow + 16, ch));
            Bh[2][0] = tb[0]; Bh[2][1] = tb[2]; Bh[3][0] = tb[1]; Bh[3][1] = tb[3];
            ldm_x4(tb, swaddr(sb + OFF_WL, nrow, ch));
            Bl[0][0] = tb[0]; Bl[0][1] = tb[2]; Bl[1][0] = tb[1]; Bl[1][1] = tb[3];
            ldm_x4(tb, swaddr(sb + OFF_WL, nrow + 16, ch));
            Bl[2][0] = tb[0]; Bl[2][1] = tb[2]; Bl[3][0] = tb[1]; Bl[3][1] = tb[3];

            #pragma unroll
            for (int mi = 0; mi < 2; mi++)
                #pragma unroll
                for (int nf = 0; nf < 4; nf++) {
                    mma16816(acc[mi][nf], Ah[mi], Bh[nf]);
                    mma16816(acc[mi][nf], Al[mi], Bh[nf]);
                    mma16816(acc[mi][nf], Ah[mi], Bl[nf]);
                }
        }

        // ---- epilogue: u -> fp16 half2 stores, v -> fp32 float2 stores ----
        #pragma unroll
        for (int mi = 0; mi < 2; mi++) {
            int row0 = nodebase + wm * 32 + mi * 16 + g8;
            #pragma unroll
            for (int nf = 0; nf < 4; nf++) {
                int cg = by * 128 + wn * 32 + nf * 8 + 2 * t4;
                if (cg < NH) {
                    __half* dp = uout + cg;
                    if (row0 < NN)
                        *(half2*)(dp + (size_t)row0 * NH) =
                            __floats2half2_rn(acc[mi][nf][0], acc[mi][nf][1]);
                    if (row0 + 8 < NN)
                        *(half2*)(dp + (size_t)(row0 + 8) * NH) =
                            __floats2half2_rn(acc[mi][nf][2], acc[mi][nf][3]);
                } else {
                    float* dp = vout + (cg - NH);
                    if (row0 < NN)
                        *(float2*)(dp + (size_t)row0 * NH) =
                            make_float2(acc[mi][nf][0], acc[mi][nf][1]);
                    if (row0 + 8 < NN)
                        *(float2*)(dp + (size_t)(row0 + 8) * NH) =
                            make_float2(acc[mi][nf][2], acc[mi][nf][3]);
                }
            }
        }
    }
}

// ---------------- fused mean-aggregate + bias + BN + ReLU (layers 1,2) ----------------
// u rows are fp16: 128 halves = 256B; lane reads uint2 (4 halves) per neighbor.
__global__ void k_agg_bn(const __half* __restrict__ u, const float* __restrict__ v,
                         const float* __restrict__ bias, const float* __restrict__ gam,
                         const float* __restrict__ bet, const float* __restrict__ rmean,
                         const float* __restrict__ rvar, float* __restrict__ hout)
{
    int gw = (blockIdx.x * blockDim.x + threadIdx.x) >> 5;
    int lane = threadIdx.x & 31;
    if (gw >= NN) return;
    int s0 = g_rowptr[gw], s1 = g_rowptr[gw + 1];
    const uint2* ub = (const uint2*)u;   // row stride = 32 uint2
    float4 acc = make_float4(0.f, 0.f, 0.f, 0.f);
    for (int b = s0; b < s1; b += 32) {
        int cnt = s1 - b; if (cnt > 32) cnt = 32;
        int idxv = (lane < cnt) ? g_col[b + lane] : 0;
        for (int j = 0; j < cnt; j++) {
            int s = __shfl_sync(~0u, idxv, j);
            uint2 t = ub[(size_t)s * 32 + lane];
            float2 f0 = __half22float2(*(const half2*)&t.x);
            float2 f1 = __half22float2(*(const half2*)&t.y);
            acc.x += f0.x; acc.y += f0.y; acc.z += f1.x; acc.w += f1.y;
        }
    }
    float iv = g_invdeg[gw];
    int cb = lane * 4;
    float4 vv = *(const float4*)(v + (size_t)gw * HID + cb);
    float4 bb = *(const float4*)(bias + cb);
    float4 gg = *(const float4*)(gam + cb);
    float4 be = *(const float4*)(bet + cb);
    float4 rm = *(const float4*)(rmean + cb);
    float4 rv = *(const float4*)(rvar + cb);
    float4 o;
    o.x = fmaxf((acc.x * iv + bb.x + vv.x - rm.x) * (gg.x * rsqrtf(rv.x + BNEPS)) + be.x, 0.f);
    o.y = fmaxf((acc.y * iv + bb.y + vv.y - rm.y) * (gg.y * rsqrtf(rv.y + BNEPS)) + be.y, 0.f);
    o.z = fmaxf((acc.z * iv + bb.z + vv.z - rm.z) * (gg.z * rsqrtf(rv.z + BNEPS)) + be.z, 0.f);
    o.w = fmaxf((acc.w * iv + bb.w + vv.w - rm.w) * (gg.w * rsqrtf(rv.w + BNEPS)) + be.w, 0.f);
    *(float4*)(hout + (size_t)gw * HID + cb) = o;
}

// ---------------- layer 3: mean-aggregate(p fp16) + b3 + r, log_softmax ----------------
__global__ void k_agg_lsm(const __half* __restrict__ p, const float* __restrict__ r,
                          const float* __restrict__ b3, float* __restrict__ out)
{
    int gw = (blockIdx.x * blockDim.x + threadIdx.x) >> 5;
    int lane = threadIdx.x & 31;
    if (gw >= NN) return;
    int s0 = g_rowptr[gw], s1 = g_rowptr[gw + 1];
    const uint32_t* pb = (const uint32_t*)p;  // row stride = 32 uint32 (64 halves)
    float ax = 0.f, ay = 0.f;
    for (int b = s0; b < s1; b += 32) {
        int cnt = s1 - b; if (cnt > 32) cnt = 32;
        int idxv = (lane < cnt) ? g_col[b + lane] : 0;
        for (int j = 0; j < cnt; j++) {
            int s = __shfl_sync(~0u, idxv, j);
            uint32_t t = pb[(size_t)s * 32 + lane];
            float2 f = __half22float2(*(const half2*)&t);
            ax += f.x; ay += f.y;
        }
    }
    float iv = g_invdeg[gw];
    float2 rr = *(const float2*)(r + (size_t)gw * OUTC + lane * 2);
    float2 bb = *(const float2*)(b3 + lane * 2);
    float l0 = ax * iv + bb.x + rr.x;
    float l1 = ay * iv + bb.y + rr.y;
    float m = fmaxf(l0, l1);
    #pragma unroll
    for (int o = 16; o; o >>= 1) m = fmaxf(m, __shfl_xor_sync(~0u, m, o));
    float s = expf(l0 - m) + expf(l1 - m);
    #pragma unroll
    for (int o = 16; o; o >>= 1) s += __shfl_xor_sync(~0u, s, o);
    float lse = m + logf(s);
    float2 o2; o2.x = l0 - lse; o2.y = l1 - lse;
    *(float2*)(out + (size_t)gw * OUTC + lane * 2) = o2;
}

// ---------------- launch ----------------
extern "C" void kernel_launch(void* const* d_in, const int* in_sizes, int n_in,
                              void* d_out, int out_size)
{
    const float* x   = (const float*)d_in[0];
    const int*   src = (const int*)d_in[1];
    const int*   dst = (const int*)d_in[2];
    const float* W1l = (const float*)d_in[3];
    const float* W1r = (const float*)d_in[4];
    const float* b1  = (const float*)d_in[5];
    const float* g1  = (const float*)d_in[6];
    const float* be1 = (const float*)d_in[7];
    const float* rm1 = (const float*)d_in[8];
    const float* rv1 = (const float*)d_in[9];
    const float* W2l = (const float*)d_in[10];
    const float* W2r = (const float*)d_in[11];
    const float* b2  = (const float*)d_in[12];
    const float* g2  = (const float*)d_in[13];
    const float* be2 = (const float*)d_in[14];
    const float* rm2 = (const float*)d_in[15];
    const float* rv2 = (const float*)d_in[16];
    const float* W3l = (const float*)d_in[17];
    const float* W3r = (const float*)d_in[18];
    const float* b3  = (const float*)d_in[19];
    float* out = (float*)d_out;

    __half* u; float *v, *h;
    cudaGetSymbolAddress((void**)&u, g_u);
    cudaGetSymbolAddress((void**)&v, g_v);
    cudaGetSymbolAddress((void**)&h, g_h);

    // one-time host-side objects (created on first/correctness call, reused; never during capture)
    static cudaStream_t s2 = nullptr;
    static cudaEvent_t ev_fork = nullptr, ev_join = nullptr;
    if (!s2) {
        cudaStreamCreateWithFlags(&s2, cudaStreamNonBlocking);
        cudaEventCreateWithFlags(&ev_fork, cudaEventDisableTiming);
        cudaEventCreateWithFlags(&ev_join, cudaEventDisableTiming);
    }

    const int NB = (NN + 1023) >> 10;
    const int SMEM = 131072;
    cudaFuncSetAttribute(k_mma_gemm<256>, cudaFuncAttributeMaxDynamicSharedMemorySize, SMEM);
    cudaFuncSetAttribute(k_mma_gemm<128>, cudaFuncAttributeMaxDynamicSharedMemorySize, SMEM);

    const int AGG_BLOCKS = (NN * 32 + 255) / 256;

    // ---- fork: CSR build on s2, layer-1 GEMM on main stream, join before agg ----
    cudaEventRecord(ev_fork, 0);
    cudaStreamWaitEvent(s2, ev_fork, 0);
    k_zero_deg<<<(NN + 255) / 256, 256, 0, s2>>>();
    k_count<<<(EE + 255) / 256, 256, 0, s2>>>(dst);
    k_scan_block<<<NB, 1024, 0, s2>>>();
    k_scan_tot<<<1, 128, 0, s2>>>(NB);
    k_finalize<<<(NN + 255) / 256, 256, 0, s2>>>();
    k_fill<<<(EE + 255) / 256, 256, 0, s2>>>(src, dst);
    cudaEventRecord(ev_join, s2);

    // Layer 1 GEMM overlaps CSR build
    k_mma_gemm<256><<<dim3(74, 2), 512, SMEM>>>(x, W1l, W1r, u, v);
    cudaStreamWaitEvent(0, ev_join, 0);
    k_agg_bn<<<AGG_BLOCKS, 256>>>(u, v, b1, g1, be1, rm1, rv1, h);
    // Layer 2
    k_mma_gemm<256><<<dim3(74, 2), 512, SMEM>>>(h, W2l, W2r, u, v);
    k_agg_bn<<<AGG_BLOCKS, 256>>>(u, v, b2, g2, be2, rm2, rv2, h);
    // Layer 3: project h -> [p|r] (64 each), aggregate p, add b3+r, log_softmax
    k_mma_gemm<128><<<dim3(148, 1), 512, SMEM>>>(h, W3l, W3r, u, v);
    k_agg_lsm<<<AGG_BLOCKS, 256>>>(u, v, b3, out);
}